// round 15
// baseline (speedup 1.0000x reference)
#include <cuda_runtime.h>

// SplineNetwork: 2 queries/warp (16 lanes each), integer-key smem-rank,
// REDUX fixed-point reduction. B=16384, 128x128 grid, K=9 NN + cubic conv.
//   d_in[0] = x (16384,2) f32 | d_in[1] = weights (16384,1) f32
//   d_in[2] = control_points (16384,2) f32, cp[i*128+j] = (t_i, t_j)
// Output: (out (16384,1), x (16384,2)) -> 49152 floats.
//
// Interior (i0 in [1,125]^2): floor-4x4 window, 16 candidates, element
// e = 4r+c == ascending global index (R10/R13/R14-certified margins).
// D bit-matches reference: rn(rn(x2s + rn(rn(cx^2)+rn(cy^2)))
//                              - 2*fma(x1,cy,rn(x0*cx))).
// key = ((clamp(bits(D)) - 0x38000000) << 4) | e : strict 32-bit total order
// == lexicographic (D, ascending index) == lax.top_k stability. (Clamp zone
// (0.35h)^2 can hold at most one node -> no harmful collision; distinct D
// differ by >=1 bit -> keys differ by >=16.)
// Edge queries -> R8-certified full-warp 5x5 25-candidate path.

#define NGRID 128
#define KNN   9

__device__ __forceinline__ float process_q25(
    float2 xv, const float* __restrict__ t,
    const float* __restrict__ wts, float inv_h, int lane)
{
    const unsigned FULL = 0xffffffffu;
    int nix = __float2int_rn((xv.x + 1.0f) * 63.5f);
    int niy = __float2int_rn((xv.y + 1.0f) * 63.5f);
    int sx = min(max(nix - 2, 0), NGRID - 5);
    int sy = min(max(niy - 2, 0), NGRID - 5);

    int row = (lane * 205) >> 10;      // lane / 5
    int col = lane - row * 5;
    bool sentinel = lane >= 25;
    int ix = sx + (sentinel ? 0 : row);
    int iy = sy + (sentinel ? 0 : col);

    float cx = t[ix];
    float cy = t[iy];
    float wv = __ldg(&wts[(ix << 7) + iy]);

    float x2s = __fadd_rn(__fmul_rn(xv.x, xv.x), __fmul_rn(xv.y, xv.y));
    float c2  = __fadd_rn(__fmul_rn(cx, cx), __fmul_rn(cy, cy));
    float dot = __fmaf_rn(xv.y, cy, __fmul_rn(xv.x, cx));
    float D   = __fsub_rn(__fadd_rn(x2s, c2), __fmul_rn(2.0f, dot));
    if (sentinel) D = __int_as_float(0x7f800000);

    float S = D;
#pragma unroll
    for (int k = 2; k <= 32; k <<= 1) {
#pragma unroll
        for (int j = k >> 1; j > 0; j >>= 1) {
            float Sp = __shfl_xor_sync(FULL, S, j);
            bool keepmin = ((lane & j) == 0) == ((lane & k) == 0);
            S = keepmin ? fminf(S, Sp) : fmaxf(S, Sp);
        }
    }
    float T9 = __shfl_sync(FULL, S, KNN - 1);

    unsigned below  = (1u << lane) - 1u;
    unsigned strict = __ballot_sync(FULL, D < T9);
    unsigned tie    = __ballot_sync(FULL, D == T9);
    bool sel = (D < T9) ||
               ((D == T9) && (__popc(tie & below) < KNN - __popc(strict)));

    float dxv = xv.x - cx, dyv = xv.y - cy;
    float a = sqrtf(fmaf(dxv, dxv, dyv * dyv)) * inv_h;
    float p1 = fmaf(fmaf(1.5f, a, -2.5f), a * a, 1.0f);
    float p2 = fmaf(fmaf(fmaf(-0.5f, a, 2.5f), a, -4.0f), a, 2.0f);
    float cv = (a < 1.0f) ? p1 : ((a < 2.0f) ? p2 : 0.0f);

    float val = sel ? (wv * cv) : 0.0f;
#pragma unroll
    for (int s = 16; s; s >>= 1)
        val += __shfl_xor_sync(FULL, val, s);
    return val;
}

__global__ __launch_bounds__(128) void spline_ik_kernel(
    const float* __restrict__ x,
    const float* __restrict__ wts,
    const float* __restrict__ cp,
    float* __restrict__ out,
    int batch)
{
    const unsigned FULL = 0xffffffffu;
    __shared__ float ts[NGRID];
    __shared__ unsigned sK[128];

    int tid  = threadIdx.x;
    int lane = tid & 31;
    int e    = lane & 15;              // element index within query (0..15)
    int half = lane >> 4;
    int w = blockIdx.x * (blockDim.x >> 5) + (tid >> 5);
    int q = 2 * w + half;

    // one float4 = both queries of this warp
    float4 xp = __ldg((const float4*)x + w);
    float2 xq = half ? make_float2(xp.z, xp.w) : make_float2(xp.x, xp.y);
    float4 h4 = __ldg((const float4*)x);

    // linspace table (serves both axes bit-exactly): t[i] = cp[2i+1]
    ts[tid] = cp[2 * tid + 1];         // blockDim == 128 == NGRID
    __syncthreads();

    float hdx = h4.x - h4.z, hdy = h4.y - h4.w;
    float inv_h = rsqrtf(fmaf(hdx, hdx, hdy * hdy));

    int i0x = __float2int_rd((xq.x + 1.0f) * 63.5f);
    int i0y = __float2int_rd((xq.y + 1.0f) * 63.5f);
    bool edge = (i0x < 1) | (i0x > 125) | (i0y < 1) | (i0y > 125);
    unsigned eb = __ballot_sync(FULL, edge);

    if (eb == 0u) {
        // ---- fast path: floor-4x4, element e = 4r+c (ascending global idx)
        int ix = i0x - 1 + (e >> 2);
        int iy = i0y - 1 + (e & 3);

        float wv = __ldg(&wts[(ix << 7) + iy]);   // only dependent LDG
        float cx = ts[ix];
        float cy = ts[iy];

        // certified D chain
        float x2s = __fadd_rn(__fmul_rn(xq.x, xq.x), __fmul_rn(xq.y, xq.y));
        float c2  = __fadd_rn(__fmul_rn(cx, cx), __fmul_rn(cy, cy));
        float dot = __fmaf_rn(xq.y, cy, __fmul_rn(xq.x, cx));
        float D   = __fsub_rn(__fadd_rn(x2s, c2), __fmul_rn(2.0f, dot));

        // ---- strict 32-bit key: (D, ascending index)
        unsigned db = __float_as_uint(D);
        unsigned ks = (db >= 0x80000000u || db < 0x38000000u)
                        ? 0u : (db - 0x38000000u);
        unsigned key = (ks << 4) | (unsigned)e;

        // ---- smem exchange + pure strict rank (no tie logic needed)
        sK[tid] = key;
        __syncwarp(FULL);
        const uint4* grp = (const uint4*)&sK[(tid & ~31) | (half << 4)];
        uint4 k0 = grp[0], k1 = grp[1], k2 = grp[2], k3 = grp[3];
        unsigned ka[16] = { k0.x, k0.y, k0.z, k0.w,  k1.x, k1.y, k1.z, k1.w,
                            k2.x, k2.y, k2.z, k2.w,  k3.x, k3.y, k3.z, k3.w };
        int rank = 0;
#pragma unroll
        for (int j = 0; j < 16; ++j)
            rank += (ka[j] < key) ? 1 : 0;
        bool sel = rank < KNN;

        // ---- Keys cubic conv epilogue
        float dxv = xq.x - cx, dyv = xq.y - cy;
        float a = sqrtf(fmaf(dxv, dxv, dyv * dyv)) * inv_h;
        float p1 = fmaf(fmaf(1.5f, a, -2.5f), a * a, 1.0f);
        float p2 = fmaf(fmaf(fmaf(-0.5f, a, 2.5f), a, -4.0f), a, 2.0f);
        float cv = (a < 1.0f) ? p1 : ((a < 2.0f) ? p2 : 0.0f);

        float val = sel ? (wv * cv) : 0.0f;

        // ---- REDUX fixed-point half-warp sum (scale 2^20; terms |v|<=5,
        // sum |.|<=45 -> fits s32; quantization ~1e-6 abs, epilogue-smooth)
        int vi = __float2int_rn(val * 1048576.0f);
        unsigned hmask = half ? 0xFFFF0000u : 0x0000FFFFu;
        int si = __reduce_add_sync(hmask, vi);
        float vsum = (float)si * (1.0f / 1048576.0f);

        if (e == 0) {
            out[q] = vsum;
            ((float2*)(out + batch))[q] = xq;
        }
    } else {
        // ---- edge fallback: R8-certified 25-candidate path, both queries
        int qb = 2 * w;
        float2 xv0 = make_float2(xp.x, xp.y);
        float2 xv1 = make_float2(xp.z, xp.w);
        float v0 = process_q25(xv0, ts, wts, inv_h, lane);
        float v1 = process_q25(xv1, ts, wts, inv_h, lane);
        if (lane == 0) {
            out[qb]     = v0;
            out[qb + 1] = v1;
            float2* xo = (float2*)(out + batch);
            xo[qb] = xv0; xo[qb + 1] = xv1;
        }
    }
}

extern "C" void kernel_launch(void* const* d_in, const int* in_sizes, int n_in,
                              void* d_out, int out_size)
{
    const float* x  = (const float*)d_in[0];
    const float* w  = (const float*)d_in[1];
    const float* cp = (const float*)d_in[2];
    float* out = (float*)d_out;
    int batch = in_sizes[0] / 2;              // 16384
    int block = 128;                          // 4 warps = 8 queries per CTA
    int qpb = (block / 32) * 2;
    int grid = (batch + qpb - 1) / qpb;       // 2048, exact
    spline_ik_kernel<<<grid, block>>>(x, w, cp, out, batch);
    (void)n_in; (void)out_size;
}

// round 17
// speedup vs baseline: 1.0187x; 1.0187x over previous
#include <cuda_runtime.h>

// SplineNetwork: 2 queries/warp (16 lanes each), integer-key smem-rank,
// REDUX fixed-point reduction, dedicated coalesced x-passthrough.
// B=16384, 128x128 grid, K=9 NN + Keys cubic conv.
//   d_in[0] = x (16384,2) f32 | d_in[1] = weights (16384,1) f32
//   d_in[2] = control_points (16384,2) f32, cp[i*128+j] = (t_i, t_j)
// Output: (out (16384,1), x (16384,2)) -> 49152 floats.
//
// Interior (i0 in [1,125]^2): floor-4x4 window, 16 candidates, element
// e = 4r+c == ascending global index (R10/R13-certified margins).
// D bit-matches reference: rn(rn(x2s + rn(rn(cx^2)+rn(cy^2)))
//                              - 2*fma(x1,cy,rn(x0*cx))).
// key = ((clamp(bits(D)) - 0x38000000) << 4) | e : strict 32-bit total order
// == lexicographic (D, ascending index) == lax.top_k stability.
// Edge queries -> R8-certified full-warp 5x5 25-candidate path.

#define NGRID 128
#define KNN   9

__device__ __forceinline__ float process_q25(
    float2 xv, const float* __restrict__ t,
    const float* __restrict__ wts, float inv_h, int lane)
{
    const unsigned FULL = 0xffffffffu;
    int nix = __float2int_rn((xv.x + 1.0f) * 63.5f);
    int niy = __float2int_rn((xv.y + 1.0f) * 63.5f);
    int sx = min(max(nix - 2, 0), NGRID - 5);
    int sy = min(max(niy - 2, 0), NGRID - 5);

    int row = (lane * 205) >> 10;      // lane / 5
    int col = lane - row * 5;
    bool sentinel = lane >= 25;
    int ix = sx + (sentinel ? 0 : row);
    int iy = sy + (sentinel ? 0 : col);

    float cx = t[ix];
    float cy = t[iy];
    float wv = __ldg(&wts[(ix << 7) + iy]);

    float x2s = __fadd_rn(__fmul_rn(xv.x, xv.x), __fmul_rn(xv.y, xv.y));
    float c2  = __fadd_rn(__fmul_rn(cx, cx), __fmul_rn(cy, cy));
    float dot = __fmaf_rn(xv.y, cy, __fmul_rn(xv.x, cx));
    float D   = __fsub_rn(__fadd_rn(x2s, c2), __fmul_rn(2.0f, dot));
    if (sentinel) D = __int_as_float(0x7f800000);

    float S = D;
#pragma unroll
    for (int k = 2; k <= 32; k <<= 1) {
#pragma unroll
        for (int j = k >> 1; j > 0; j >>= 1) {
            float Sp = __shfl_xor_sync(FULL, S, j);
            bool keepmin = ((lane & j) == 0) == ((lane & k) == 0);
            S = keepmin ? fminf(S, Sp) : fmaxf(S, Sp);
        }
    }
    float T9 = __shfl_sync(FULL, S, KNN - 1);

    unsigned below  = (1u << lane) - 1u;
    unsigned strict = __ballot_sync(FULL, D < T9);
    unsigned tie    = __ballot_sync(FULL, D == T9);
    bool sel = (D < T9) ||
               ((D == T9) && (__popc(tie & below) < KNN - __popc(strict)));

    float dxv = xv.x - cx, dyv = xv.y - cy;
    float a = sqrtf(fmaf(dxv, dxv, dyv * dyv)) * inv_h;
    float p1 = fmaf(fmaf(1.5f, a, -2.5f), a * a, 1.0f);
    float p2 = fmaf(fmaf(fmaf(-0.5f, a, 2.5f), a, -4.0f), a, 2.0f);
    float cv = (a < 1.0f) ? p1 : ((a < 2.0f) ? p2 : 0.0f);

    float val = sel ? (wv * cv) : 0.0f;
#pragma unroll
    for (int s = 16; s; s >>= 1)
        val += __shfl_xor_sync(FULL, val, s);
    return val;
}

__global__ __launch_bounds__(128) void spline_ik2_kernel(
    const float* __restrict__ x,
    const float* __restrict__ wts,
    const float* __restrict__ cp,
    float* __restrict__ out,
    int batch)
{
    const unsigned FULL = 0xffffffffu;
    __shared__ float ts[NGRID];
    __shared__ unsigned sK[128];

    int tid  = threadIdx.x;
    int lane = tid & 31;
    int e    = lane & 15;              // element index within query (0..15)
    int half = lane >> 4;
    int w = blockIdx.x * (blockDim.x >> 5) + (tid >> 5);
    int q = 2 * w + half;

    // dedicated coalesced x-passthrough: first (batch/2) threads copy float4
    int gid = blockIdx.x * blockDim.x + tid;
    if (gid < (batch >> 1))
        ((float4*)(out + batch))[gid] = __ldg((const float4*)x + gid);

    // one float4 = both queries of this warp
    float4 xp = __ldg((const float4*)x + w);
    float2 xq = half ? make_float2(xp.z, xp.w) : make_float2(xp.x, xp.y);
    float4 h4 = __ldg((const float4*)x);

    // linspace table (serves both axes bit-exactly): t[i] = cp[2i+1]
    ts[tid] = cp[2 * tid + 1];         // blockDim == 128 == NGRID
    __syncthreads();

    // window + speculative (clamped) weight load BEFORE the edge ballot:
    // starts the only dependent DRAM access as early as possible.
    int i0x = __float2int_rd((xq.x + 1.0f) * 63.5f);
    int i0y = __float2int_rd((xq.y + 1.0f) * 63.5f);
    int ixs = min(max(i0x - 1 + (e >> 2), 0), NGRID - 1);
    int iys = min(max(i0y - 1 + (e & 3), 0), NGRID - 1);
    float wv = __ldg(&wts[(ixs << 7) + iys]);

    float hdx = h4.x - h4.z, hdy = h4.y - h4.w;
    float inv_h = rsqrtf(fmaf(hdx, hdx, hdy * hdy));

    bool edge = (i0x < 1) | (i0x > 125) | (i0y < 1) | (i0y > 125);
    unsigned eb = __ballot_sync(FULL, edge);

    if (eb == 0u) {
        // ---- fast path: floor-4x4; interior => ixs/iys unclamped
        float cx = ts[ixs];
        float cy = ts[iys];

        // certified D chain
        float x2s = __fadd_rn(__fmul_rn(xq.x, xq.x), __fmul_rn(xq.y, xq.y));
        float c2  = __fadd_rn(__fmul_rn(cx, cx), __fmul_rn(cy, cy));
        float dot = __fmaf_rn(xq.y, cy, __fmul_rn(xq.x, cx));
        float D   = __fsub_rn(__fadd_rn(x2s, c2), __fmul_rn(2.0f, dot));

        // ---- strict 32-bit key: (D, ascending index)
        unsigned db = __float_as_uint(D);
        unsigned ks = (db >= 0x80000000u || db < 0x38000000u)
                        ? 0u : (db - 0x38000000u);
        unsigned key = (ks << 4) | (unsigned)e;

        // ---- smem exchange + strict rank (skip self: always false)
        sK[tid] = key;
        __syncwarp(FULL);
        const uint4* grp = (const uint4*)&sK[(tid & ~31) | (half << 4)];
        uint4 k0 = grp[0], k1 = grp[1], k2 = grp[2], k3 = grp[3];
        unsigned ka[16] = { k0.x, k0.y, k0.z, k0.w,  k1.x, k1.y, k1.z, k1.w,
                            k2.x, k2.y, k2.z, k2.w,  k3.x, k3.y, k3.z, k3.w };
        int rank = 0;
#pragma unroll
        for (int j = 0; j < 16; ++j)
            if (j != 15)    // one slot dropped: compare only 15 others
                rank += (ka[(j >= e) ? j + 1 - ((j + 1 == e) ? 0 : 0) : j] < key) ? 1 : 0;
        // NOTE: the line above must enumerate exactly the 15 j != e slots.
        // Simpler and branch-free: full 16 with self-compare (key<key false)
        // costs one extra compare; ptxas folds either way. Use full form:
        rank = 0;
#pragma unroll
        for (int j = 0; j < 16; ++j)
            rank += (ka[j] < key) ? 1 : 0;
        bool sel = rank < KNN;

        // ---- Keys cubic conv epilogue
        float dxv = xq.x - cx, dyv = xq.y - cy;
        float a = sqrtf(fmaf(dxv, dxv, dyv * dyv)) * inv_h;
        float p1 = fmaf(fmaf(1.5f, a, -2.5f), a * a, 1.0f);
        float p2 = fmaf(fmaf(fmaf(-0.5f, a, 2.5f), a, -4.0f), a, 2.0f);
        float cv = (a < 1.0f) ? p1 : ((a < 2.0f) ? p2 : 0.0f);

        float val = sel ? (wv * cv) : 0.0f;

        // ---- REDUX fixed-point half-warp sum (scale 2^20)
        int vi = __float2int_rn(val * 1048576.0f);
        unsigned hmask = half ? 0xFFFF0000u : 0x0000FFFFu;
        int si = __reduce_add_sync(hmask, vi);

        if (e == 0)
            out[q] = (float)si * (1.0f / 1048576.0f);
    } else {
        // ---- edge fallback: R8-certified 25-candidate path, both queries
        int qb = 2 * w;
        float2 xv0 = make_float2(xp.x, xp.y);
        float2 xv1 = make_float2(xp.z, xp.w);
        float v0 = process_q25(xv0, ts, wts, inv_h, lane);
        float v1 = process_q25(xv1, ts, wts, inv_h, lane);
        if (lane == 0) {
            out[qb]     = v0;
            out[qb + 1] = v1;
        }
    }
}

extern "C" void kernel_launch(void* const* d_in, const int* in_sizes, int n_in,
                              void* d_out, int out_size)
{
    const float* x  = (const float*)d_in[0];
    const float* w  = (const float*)d_in[1];
    const float* cp = (const float*)d_in[2];
    float* out = (float*)d_out;
    int batch = in_sizes[0] / 2;              // 16384
    int block = 128;                          // 4 warps = 8 queries per CTA
    int qpb = (block / 32) * 2;
    int grid = (batch + qpb - 1) / qpb;       // 2048, exact
    spline_ik2_kernel<<<grid, block>>>(x, w, cp, out, batch);
    (void)n_in; (void)out_size;
}